// round 5
// baseline (speedup 1.0000x reference)
#include <cuda_runtime.h>
#include <cstdint>

#define EE 256
#define HN 8
#define DH 32
#define LLAYERS 4
#define FFD 1024
#define NQ 64
#define PAIRS 2016
#define PPAD 2048
#define MMEM 4096
#define TTXT 32

// ---------------- scratch (static device globals; allocation-free) ----------------
__device__ float g_pairconcat[PPAD * 512];
__device__ float g_q[PPAD * EE];
__device__ float g_qh[PPAD * EE];
__device__ float g_mem[MMEM * EE];
__device__ float g_k[MMEM * EE];
__device__ float g_v[MMEM * EE];
__device__ float g_attn[PPAD * EE];
__device__ float g_proj[PPAD * EE];
__device__ float g_ffb[PPAD * FFD];
__device__ float g_text[TTXT * EE];
__device__ int   g_rowi[PAIRS];
__device__ int   g_coli[PAIRS];
__device__ float g_refx[PAIRS];
__device__ float g_refy[PAIRS];

__device__ __forceinline__ void mma_tf32(float* c, uint32_t a0, uint32_t a1,
                                         uint32_t a2, uint32_t a3,
                                         uint32_t b0, uint32_t b1) {
    asm volatile(
        "mma.sync.aligned.m16n8k8.row.col.f32.tf32.tf32.f32 "
        "{%0,%1,%2,%3}, {%4,%5,%6,%7}, {%8,%9}, {%0,%1,%2,%3};\n"
        : "+f"(c[0]), "+f"(c[1]), "+f"(c[2]), "+f"(c[3])
        : "r"(a0), "r"(a1), "r"(a2), "r"(a3), "r"(b0), "r"(b1));
}

__device__ __forceinline__ uint32_t f2tf(float x) {
    uint32_t r;
    asm("cvt.rna.tf32.f32 %0, %1;" : "=r"(r) : "f"(x));
    return r;
}

// ---------------- 3x-tf32 split GEMM: C = A[M,K] @ B[K,N] + bias (opt ReLU) -------
// 64x64 tile, BK=32, 128 threads; hi/lo split at smem-store; register prefetch.
#define GPA 36
#define GPB 68
template <bool RELU>
__global__ void __launch_bounds__(128) gemm_tc3(const float* __restrict__ A,
                                                const float* __restrict__ B,
                                                const float* __restrict__ bias,
                                                float* __restrict__ C,
                                                int M, int N, int K) {
    __shared__ uint32_t AsH[64][GPA], AsL[64][GPA];
    __shared__ uint32_t BsH[32][GPB], BsL[32][GPB];
    const int tid  = threadIdx.x;
    const int warp = tid >> 5, lane = tid & 31;
    const int qd = lane >> 2, qt = lane & 3;
    const int bm = blockIdx.y << 6, bn = blockIdx.x << 6;
    const int r0 = (warp << 4) + qd;

    // per-thread load coordinates
    int arw[4], ac4[4], bkr[4], bn4[4];
#pragma unroll
    for (int i = 0; i < 4; i++) {
        int idx = tid + i * 128;
        arw[i] = idx >> 3;  ac4[i] = (idx & 7) << 2;
        bkr[i] = idx >> 4;  bn4[i] = (idx & 15) << 2;
    }
    float4 ra[4], rb[4];
#pragma unroll
    for (int i = 0; i < 4; i++) {
        int gr = bm + arw[i]; if (gr >= M) gr = M - 1;
        ra[i] = *(const float4*)(A + (size_t)gr * K + ac4[i]);
        rb[i] = *(const float4*)(B + (size_t)bkr[i] * N + bn + bn4[i]);
    }

    float acc[8][4] = {};
    for (int k0 = 0; k0 < K; k0 += 32) {
        // store current tile with hi/lo split
#pragma unroll
        for (int i = 0; i < 4; i++) {
            float vals[4] = {ra[i].x, ra[i].y, ra[i].z, ra[i].w};
#pragma unroll
            for (int u = 0; u < 4; u++) {
                uint32_t h = f2tf(vals[u]);
                AsH[arw[i]][ac4[i] + u] = h;
                AsL[arw[i]][ac4[i] + u] = f2tf(vals[u] - __uint_as_float(h));
            }
            float wv[4] = {rb[i].x, rb[i].y, rb[i].z, rb[i].w};
#pragma unroll
            for (int u = 0; u < 4; u++) {
                uint32_t h = f2tf(wv[u]);
                BsH[bkr[i]][bn4[i] + u] = h;
                BsL[bkr[i]][bn4[i] + u] = f2tf(wv[u] - __uint_as_float(h));
            }
        }
        __syncthreads();
        // prefetch next tile (overlaps with mma below)
        if (k0 + 32 < K) {
#pragma unroll
            for (int i = 0; i < 4; i++) {
                int gr = bm + arw[i]; if (gr >= M) gr = M - 1;
                ra[i] = *(const float4*)(A + (size_t)gr * K + k0 + 32 + ac4[i]);
                rb[i] = *(const float4*)(B + (size_t)(k0 + 32 + bkr[i]) * N + bn + bn4[i]);
            }
        }
#pragma unroll
        for (int kk = 0; kk < 4; kk++) {
            uint32_t ah0 = AsH[r0    ][kk * 8 + qt];
            uint32_t ah1 = AsH[r0 + 8][kk * 8 + qt];
            uint32_t ah2 = AsH[r0    ][kk * 8 + qt + 4];
            uint32_t ah3 = AsH[r0 + 8][kk * 8 + qt + 4];
            uint32_t al0 = AsL[r0    ][kk * 8 + qt];
            uint32_t al1 = AsL[r0 + 8][kk * 8 + qt];
            uint32_t al2 = AsL[r0    ][kk * 8 + qt + 4];
            uint32_t al3 = AsL[r0 + 8][kk * 8 + qt + 4];
#pragma unroll
            for (int j = 0; j < 8; j++) {
                uint32_t bh0 = BsH[kk * 8 + qt    ][j * 8 + qd];
                uint32_t bh1 = BsH[kk * 8 + qt + 4][j * 8 + qd];
                uint32_t bl0 = BsL[kk * 8 + qt    ][j * 8 + qd];
                uint32_t bl1 = BsL[kk * 8 + qt + 4][j * 8 + qd];
                mma_tf32(acc[j], ah0, ah1, ah2, ah3, bl0, bl1);
                mma_tf32(acc[j], al0, al1, al2, al3, bh0, bh1);
                mma_tf32(acc[j], ah0, ah1, ah2, ah3, bh0, bh1);
            }
        }
        __syncthreads();
    }
    const int ra0 = bm + r0, ra1 = ra0 + 8;
#pragma unroll
    for (int j = 0; j < 8; j++) {
        int col = bn + j * 8 + (qt << 1);
        float b0 = bias[col], b1 = bias[col + 1];
        if (ra0 < M) {
            float v0 = acc[j][0] + b0, v1 = acc[j][1] + b1;
            if (RELU) { v0 = fmaxf(v0, 0.f); v1 = fmaxf(v1, 0.f); }
            *(float2*)(C + (size_t)ra0 * N + col) = make_float2(v0, v1);
        }
        if (ra1 < M) {
            float v2 = acc[j][2] + b0, v3 = acc[j][3] + b1;
            if (RELU) { v2 = fmaxf(v2, 0.f); v3 = fmaxf(v3, 0.f); }
            *(float2*)(C + (size_t)ra1 * N + col) = make_float2(v2, v3);
        }
    }
}

// ---------------- tf32 tensor-core flash attention (1-pass tf32) ------------------
#define PAD_Q 36
#define PAD_K 68
#define PAD_V 36
#define PAD_P 68

__global__ void __launch_bounds__(128) flash_tc_kernel(const float* __restrict__ Q,
                                                       const float* __restrict__ Km,
                                                       const float* __restrict__ Vm,
                                                       float* __restrict__ O) {
    const int h  = blockIdx.y;
    const int pb = blockIdx.x << 6;
    __shared__ float Qs[64][PAD_Q];
    __shared__ float Ks[32][PAD_K];
    __shared__ float Vs[64][PAD_V];
    __shared__ float Ps[64][PAD_P];
    const int tid  = threadIdx.x;
    const int warp = tid >> 5, lane = tid & 31;
    const int qd = lane >> 2;
    const int qt = lane & 3;
    const int r0 = (warp << 4) + qd;

    {
        const float alpha = 0.17677669529663687f;
        int idx = tid;
#pragma unroll
        for (int i = 0; i < 4; i++, idx += 128) {
            int row = idx >> 3, c4 = (idx & 7) << 2;
            float4 v = *(const float4*)(Q + (size_t)(pb + row) * EE + h * DH + c4);
            Qs[row][c4 + 0] = v.x * alpha; Qs[row][c4 + 1] = v.y * alpha;
            Qs[row][c4 + 2] = v.z * alpha; Qs[row][c4 + 3] = v.w * alpha;
        }
    }
    float oacc[4][4] = {};
    float lsum0 = 0.f, lsum1 = 0.f;
    __syncthreads();

    for (int mb = 0; mb < MMEM; mb += 64) {
        {
            int idx = tid;
#pragma unroll
            for (int i = 0; i < 4; i++, idx += 128) {
                int m = idx >> 3, c4 = (idx & 7) << 2;
                float4 kv = *(const float4*)(Km + (size_t)(mb + m) * EE + h * DH + c4);
                Ks[c4 + 0][m] = kv.x; Ks[c4 + 1][m] = kv.y;
                Ks[c4 + 2][m] = kv.z; Ks[c4 + 3][m] = kv.w;
                *(float4*)&Vs[m][c4] = *(const float4*)(Vm + (size_t)(mb + m) * EE + h * DH + c4);
            }
        }
        __syncthreads();

        float sacc[8][4] = {};
#pragma unroll
        for (int kk = 0; kk < 4; kk++) {
            uint32_t a0 = __float_as_uint(Qs[r0    ][kk * 8 + qt]);
            uint32_t a1 = __float_as_uint(Qs[r0 + 8][kk * 8 + qt]);
            uint32_t a2 = __float_as_uint(Qs[r0    ][kk * 8 + qt + 4]);
            uint32_t a3 = __float_as_uint(Qs[r0 + 8][kk * 8 + qt + 4]);
#pragma unroll
            for (int j = 0; j < 8; j++) {
                uint32_t b0 = __float_as_uint(Ks[kk * 8 + qt    ][j * 8 + qd]);
                uint32_t b1 = __float_as_uint(Ks[kk * 8 + qt + 4][j * 8 + qd]);
                mma_tf32(sacc[j], a0, a1, a2, a3, b0, b1);
            }
        }

#pragma unroll
        for (int j = 0; j < 8; j++) {
            float e0 = __expf(sacc[j][0]), e1 = __expf(sacc[j][1]);
            float e2 = __expf(sacc[j][2]), e3 = __expf(sacc[j][3]);
            lsum0 += e0 + e1; lsum1 += e2 + e3;
            *(float2*)&Ps[r0    ][j * 8 + (qt << 1)] = make_float2(e0, e1);
            *(float2*)&Ps[r0 + 8][j * 8 + (qt << 1)] = make_float2(e2, e3);
        }
        __syncwarp();

#pragma unroll
        for (int kk = 0; kk < 8; kk++) {
            uint32_t a0 = __float_as_uint(Ps[r0    ][kk * 8 + qt]);
            uint32_t a1 = __float_as_uint(Ps[r0 + 8][kk * 8 + qt]);
            uint32_t a2 = __float_as_uint(Ps[r0    ][kk * 8 + qt + 4]);
            uint32_t a3 = __float_as_uint(Ps[r0 + 8][kk * 8 + qt + 4]);
#pragma unroll
            for (int j = 0; j < 4; j++) {
                uint32_t b0 = __float_as_uint(Vs[kk * 8 + qt    ][j * 8 + qd]);
                uint32_t b1 = __float_as_uint(Vs[kk * 8 + qt + 4][j * 8 + qd]);
                mma_tf32(oacc[j], a0, a1, a2, a3, b0, b1);
            }
        }
        __syncthreads();
    }

    lsum0 += __shfl_xor_sync(0xffffffffu, lsum0, 1);
    lsum0 += __shfl_xor_sync(0xffffffffu, lsum0, 2);
    lsum1 += __shfl_xor_sync(0xffffffffu, lsum1, 1);
    lsum1 += __shfl_xor_sync(0xffffffffu, lsum1, 2);
    float inv0 = 1.0f / lsum0, inv1 = 1.0f / lsum1;
#pragma unroll
    for (int j = 0; j < 4; j++) {
        float* op = O + (size_t)(pb + r0) * EE + h * DH + j * 8 + (qt << 1);
        *(float2*)op            = make_float2(oacc[j][0] * inv0, oacc[j][1] * inv0);
        *(float2*)(op + 8 * EE) = make_float2(oacc[j][2] * inv1, oacc[j][3] * inv1);
    }
}

// q = LayerNorm(q + resid) * g + b
__global__ void add_ln_kernel(float* __restrict__ Qb, const float* __restrict__ R,
                              const float* __restrict__ g, const float* __restrict__ b) {
    const int p = blockIdx.x;
    const int e = threadIdx.x;
    __shared__ float sh[8];
    float x = Qb[(size_t)p * EE + e] + R[(size_t)p * EE + e];
    float s = x;
#pragma unroll
    for (int o = 16; o > 0; o >>= 1) s += __shfl_xor_sync(0xffffffffu, s, o);
    if ((e & 31) == 0) sh[e >> 5] = s;
    __syncthreads();
    float mean = (sh[0] + sh[1] + sh[2] + sh[3] + sh[4] + sh[5] + sh[6] + sh[7]) * (1.0f / 256.0f);
    float d = x - mean;
    __syncthreads();
    s = d * d;
#pragma unroll
    for (int o = 16; o > 0; o >>= 1) s += __shfl_xor_sync(0xffffffffu, s, o);
    if ((e & 31) == 0) sh[e >> 5] = s;
    __syncthreads();
    float var = (sh[0] + sh[1] + sh[2] + sh[3] + sh[4] + sh[5] + sh[6] + sh[7]) * (1.0f / 256.0f);
    Qb[(size_t)p * EE + e] = d * rsqrtf(var + 1e-5f) * g[e] + b[e];
}

__global__ void idx_kernel(const float* __restrict__ refs, int* __restrict__ rows,
                           int* __restrict__ cols, float* __restrict__ rfx,
                           float* __restrict__ rfy) {
    int p = blockIdx.x * blockDim.x + threadIdx.x;
    if (p >= PAIRS) return;
    int r = 0, off = 0;
    while (p >= off + (NQ - 1 - r)) { off += NQ - 1 - r; r++; }
    int c = r + 1 + (p - off);
    rows[p] = r; cols[p] = c;
    rfx[p] = 0.5f * (refs[r * 4 + 0] + refs[c * 4 + 0]);
    rfy[p] = 0.5f * (refs[r * 4 + 1] + refs[c * 4 + 1]);
}

__global__ void pairc_kernel(const float* __restrict__ H, const int* __restrict__ rows,
                             const int* __restrict__ cols, float* __restrict__ PC) {
    const int p = blockIdx.x;
    const int e = threadIdx.x;
    int r = rows[p], c = cols[p];
    PC[(size_t)p * 512 + e]       = H[r * EE + e];
    PC[(size_t)p * 512 + 256 + e] = H[c * EE + e];
}

__global__ void addref_kernel(float* __restrict__ Qb, const float* __restrict__ rfx,
                              const float* __restrict__ rfy, const float* __restrict__ Wref) {
    const int p = blockIdx.x;
    const int e = threadIdx.x;
    Qb[(size_t)p * EE + e] += rfx[p] * Wref[e] + rfy[p] * Wref[EE + e];
}

__global__ void score_kernel(const float* __restrict__ Qb, const float* __restrict__ Tx,
                             const float* __restrict__ lsc, const int* __restrict__ rows,
                             const int* __restrict__ cols, float* __restrict__ out) {
    const int pp = blockIdx.x;
    __shared__ float qr[EE];
    const int tid = threadIdx.x;
    qr[tid] = Qb[(size_t)pp * EE + tid];
    __syncthreads();
    const float scale = expf(lsc[0]);
    const int w = tid >> 5, lane = tid & 31;
    const int r = rows[pp], c = cols[pp];
    for (int t = w; t < TTXT; t += 8) {
        float sum = 0.0f;
#pragma unroll
        for (int i = 0; i < 8; i++)
            sum = fmaf(qr[lane + (i << 5)], Tx[(size_t)t * EE + lane + (i << 5)], sum);
#pragma unroll
        for (int o = 16; o > 0; o >>= 1) sum += __shfl_down_sync(0xffffffffu, sum, o);
        if (lane == 0) {
            float vv = sum * scale;
            out[(size_t)(r * NQ + c) * TTXT + t] = vv;
            out[(size_t)(c * NQ + r) * TTXT + t] = vv;
        }
    }
}

// ----------------------------------- launcher ------------------------------------
extern "C" void kernel_launch(void* const* d_in, const int* in_sizes, int n_in,
                              void* d_out, int out_size) {
    const float* hid    = (const float*)d_in[0];
    const float* memin  = (const float*)d_in[1];
    const float* refs   = (const float*)d_in[2];
    const float* mtext  = (const float*)d_in[3];
    const float* W_pair = (const float*)d_in[6];
    const float* b_pair = (const float*)d_in[7];
    const float* W_mem  = (const float*)d_in[8];
    const float* b_mem  = (const float*)d_in[9];
    const float* W_text = (const float*)d_in[10];
    const float* b_text = (const float*)d_in[11];
    const float* W_ref  = (const float*)d_in[12];
    const float* Wq = (const float*)d_in[13]; const float* bq = (const float*)d_in[14];
    const float* Wk = (const float*)d_in[15]; const float* bk = (const float*)d_in[16];
    const float* Wv = (const float*)d_in[17]; const float* bv = (const float*)d_in[18];
    const float* Wo = (const float*)d_in[19]; const float* bo = (const float*)d_in[20];
    const float* ln1g = (const float*)d_in[21]; const float* ln1b = (const float*)d_in[22];
    const float* ln2g = (const float*)d_in[23]; const float* ln2b = (const float*)d_in[24];
    const float* Wf1 = (const float*)d_in[25]; const float* bf1 = (const float*)d_in[26];
    const float* Wf2 = (const float*)d_in[27]; const float* bf2 = (const float*)d_in[28];
    const float* lsc = (const float*)d_in[29];
    float* out = (float*)d_out;

    float *pc, *q, *qh, *mem, *k, *v, *attn, *proj, *ffb, *text, *rfx, *rfy;
    int *rowp, *colp;
    cudaGetSymbolAddress((void**)&pc,   g_pairconcat);
    cudaGetSymbolAddress((void**)&q,    g_q);
    cudaGetSymbolAddress((void**)&qh,   g_qh);
    cudaGetSymbolAddress((void**)&mem,  g_mem);
    cudaGetSymbolAddress((void**)&k,    g_k);
    cudaGetSymbolAddress((void**)&v,    g_v);
    cudaGetSymbolAddress((void**)&attn, g_attn);
    cudaGetSymbolAddress((void**)&proj, g_proj);
    cudaGetSymbolAddress((void**)&ffb,  g_ffb);
    cudaGetSymbolAddress((void**)&text, g_text);
    cudaGetSymbolAddress((void**)&rowp, g_rowi);
    cudaGetSymbolAddress((void**)&colp, g_coli);
    cudaGetSymbolAddress((void**)&rfx,  g_refx);
    cudaGetSymbolAddress((void**)&rfy,  g_refy);

    idx_kernel<<<8, 256>>>(refs, rowp, colp, rfx, rfy);
    pairc_kernel<<<PAIRS, 256>>>(hid, rowp, colp, pc);
    gemm_tc3<false><<<dim3(4, 32), 128>>>(pc, W_pair, b_pair, q, PAIRS, EE, 512);
    addref_kernel<<<PAIRS, 256>>>(q, rfx, rfy, W_ref);
    gemm_tc3<false><<<dim3(4, 64), 128>>>(memin, W_mem, b_mem, mem, MMEM, EE, EE);
    gemm_tc3<false><<<dim3(4, 1), 128>>>(mtext, W_text, b_text, text, TTXT, EE, EE);

    for (int l = 0; l < LLAYERS; l++) {
        gemm_tc3<false><<<dim3(4, 32), 128>>>(q,   Wq + l * EE * EE, bq + l * EE, qh,  PAIRS, EE, EE);
        gemm_tc3<false><<<dim3(4, 64), 128>>>(mem, Wk + l * EE * EE, bk + l * EE, k,   MMEM, EE, EE);
        gemm_tc3<false><<<dim3(4, 64), 128>>>(mem, Wv + l * EE * EE, bv + l * EE, v,   MMEM, EE, EE);
        flash_tc_kernel<<<dim3(PPAD / 64, HN), 128>>>(qh, k, v, attn);
        gemm_tc3<false><<<dim3(4, 32), 128>>>(attn, Wo + l * EE * EE, bo + l * EE, proj, PAIRS, EE, EE);
        add_ln_kernel<<<PAIRS, 256>>>(q, proj, ln1g + l * EE, ln1b + l * EE);
        gemm_tc3<true ><<<dim3(16, 32), 128>>>(q,   Wf1 + l * EE * FFD, bf1 + l * FFD, ffb,  PAIRS, FFD, EE);
        gemm_tc3<false><<<dim3(4, 32), 128>>>(ffb, Wf2 + l * FFD * EE, bf2 + l * EE,  proj, PAIRS, EE, FFD);
        add_ln_kernel<<<PAIRS, 256>>>(q, proj, ln2g + l * EE, ln2b + l * EE);
    }

    cudaMemsetAsync(d_out, 0, (size_t)out_size * sizeof(float), 0);
    score_kernel<<<PAIRS, 256>>>(q, text, lsc, rowp, colp, out);
}

// round 6
// speedup vs baseline: 1.0048x; 1.0048x over previous
#include <cuda_runtime.h>
#include <cstdint>

#define EE 256
#define HN 8
#define DH 32
#define LLAYERS 4
#define FFD 1024
#define NQ 64
#define PAIRS 2016
#define PPAD 2048
#define MMEM 4096
#define TTXT 32

// ---------------- scratch (static device globals; allocation-free) ----------------
__device__ float g_pairconcat[PPAD * 512];
__device__ float g_q[PPAD * EE];
__device__ float g_qh[PPAD * EE];
__device__ float g_mem[MMEM * EE];
__device__ float g_kall[LLAYERS * MMEM * EE];
__device__ float g_vall[LLAYERS * MMEM * EE];
__device__ float g_attn[PPAD * EE];
__device__ float g_proj[PPAD * EE];
__device__ float g_ffb[PPAD * FFD];
__device__ float g_text[TTXT * EE];
__device__ int   g_rowi[PAIRS];
__device__ int   g_coli[PAIRS];
__device__ float g_refx[PAIRS];
__device__ float g_refy[PAIRS];

__device__ __forceinline__ void mma_tf32(float* c, uint32_t a0, uint32_t a1,
                                         uint32_t a2, uint32_t a3,
                                         uint32_t b0, uint32_t b1) {
    asm volatile(
        "mma.sync.aligned.m16n8k8.row.col.f32.tf32.tf32.f32 "
        "{%0,%1,%2,%3}, {%4,%5,%6,%7}, {%8,%9}, {%0,%1,%2,%3};\n"
        : "+f"(c[0]), "+f"(c[1]), "+f"(c[2]), "+f"(c[3])
        : "r"(a0), "r"(a1), "r"(a2), "r"(a3), "r"(b0), "r"(b1));
}

__device__ __forceinline__ uint32_t f2tf(float x) {
    uint32_t r;
    asm("cvt.rna.tf32.f32 %0, %1;" : "=r"(r) : "f"(x));
    return r;
}

// ---------------- 3x-tf32 split GEMM body: 64x64 tile, BK=32, 256 thr (8 warps) ---
// warp = 16 rows x 32 cols; hi/lo split at smem-store; register prefetch.
#define GPA 36
#define GPB 68
template <bool RELU>
__device__ __forceinline__ void gemm_body(const float* __restrict__ A,
                                          const float* __restrict__ B,
                                          const float* __restrict__ bias,
                                          float* __restrict__ C,
                                          int M, int N, int K, int bm, int bn) {
    __shared__ uint32_t AsH[64][GPA], AsL[64][GPA];
    __shared__ uint32_t BsH[32][GPB], BsL[32][GPB];
    const int tid  = threadIdx.x;
    const int warp = tid >> 5, lane = tid & 31;
    const int qd = lane >> 2, qt = lane & 3;
    const int r0 = ((warp >> 1) << 4) + qd;   // 16-row group
    const int cb = (warp & 1) << 5;           // 32-col half

    int arw[2], ac4[2], bkr[2], bn4[2];
#pragma unroll
    for (int i = 0; i < 2; i++) {
        int idx = tid + (i << 8);
        arw[i] = idx >> 3;  ac4[i] = (idx & 7) << 2;
        bkr[i] = idx >> 4;  bn4[i] = (idx & 15) << 2;
    }
    float4 ra[2], rb[2];
#pragma unroll
    for (int i = 0; i < 2; i++) {
        int gr = bm + arw[i]; if (gr >= M) gr = M - 1;
        ra[i] = *(const float4*)(A + (size_t)gr * K + ac4[i]);
        rb[i] = *(const float4*)(B + (size_t)bkr[i] * N + bn + bn4[i]);
    }

    float acc[4][4] = {};
    for (int k0 = 0; k0 < K; k0 += 32) {
#pragma unroll
        for (int i = 0; i < 2; i++) {
            float va[4] = {ra[i].x, ra[i].y, ra[i].z, ra[i].w};
#pragma unroll
            for (int u = 0; u < 4; u++) {
                uint32_t h = f2tf(va[u]);
                AsH[arw[i]][ac4[i] + u] = h;
                AsL[arw[i]][ac4[i] + u] = f2tf(va[u] - __uint_as_float(h));
            }
            float vb[4] = {rb[i].x, rb[i].y, rb[i].z, rb[i].w};
#pragma unroll
            for (int u = 0; u < 4; u++) {
                uint32_t h = f2tf(vb[u]);
                BsH[bkr[i]][bn4[i] + u] = h;
                BsL[bkr[i]][bn4[i] + u] = f2tf(vb[u] - __uint_as_float(h));
            }
        }
        __syncthreads();
        if (k0 + 32 < K) {
#pragma unroll
            for (int i = 0; i < 2; i++) {
                int gr = bm + arw[i]; if (gr >= M) gr = M - 1;
                ra[i] = *(const float4*)(A + (size_t)gr * K + k0 + 32 + ac4[i]);
                rb[i] = *(const float4*)(B + (size_t)(k0 + 32 + bkr[i]) * N + bn + bn4[i]);
            }
        }
#pragma unroll
        for (int kk = 0; kk < 4; kk++) {
            uint32_t ah0 = AsH[r0    ][kk * 8 + qt];
            uint32_t ah1 = AsH[r0 + 8][kk * 8 + qt];
            uint32_t ah2 = AsH[r0    ][kk * 8 + qt + 4];
            uint32_t ah3 = AsH[r0 + 8][kk * 8 + qt + 4];
            uint32_t al0 = AsL[r0    ][kk * 8 + qt];
            uint32_t al1 = AsL[r0 + 8][kk * 8 + qt];
            uint32_t al2 = AsL[r0    ][kk * 8 + qt + 4];
            uint32_t al3 = AsL[r0 + 8][kk * 8 + qt + 4];
#pragma unroll
            for (int j = 0; j < 4; j++) {
                int colb = cb + j * 8 + qd;
                uint32_t bh0 = BsH[kk * 8 + qt    ][colb];
                uint32_t bh1 = BsH[kk * 8 + qt + 4][colb];
                uint32_t bl0 = BsL[kk * 8 + qt    ][colb];
                uint32_t bl1 = BsL[kk * 8 + qt + 4][colb];
                mma_tf32(acc[j], ah0, ah1, ah2, ah3, bl0, bl1);
                mma_tf32(acc[j], al0, al1, al2, al3, bh0, bh1);
                mma_tf32(acc[j], ah0, ah1, ah2, ah3, bh0, bh1);
            }
        }
        __syncthreads();
    }
    const int ra0 = bm + r0, ra1 = ra0 + 8;
#pragma unroll
    for (int j = 0; j < 4; j++) {
        int col = bn + cb + j * 8 + (qt << 1);
        float b0 = bias[col], b1 = bias[col + 1];
        if (ra0 < M) {
            float v0 = acc[j][0] + b0, v1 = acc[j][1] + b1;
            if (RELU) { v0 = fmaxf(v0, 0.f); v1 = fmaxf(v1, 0.f); }
            *(float2*)(C + (size_t)ra0 * N + col) = make_float2(v0, v1);
        }
        if (ra1 < M) {
            float v2 = acc[j][2] + b0, v3 = acc[j][3] + b1;
            if (RELU) { v2 = fmaxf(v2, 0.f); v3 = fmaxf(v3, 0.f); }
            *(float2*)(C + (size_t)ra1 * N + col) = make_float2(v2, v3);
        }
    }
}

template <bool RELU>
__global__ void __launch_bounds__(256) gemm_tc3(const float* __restrict__ A,
                                                const float* __restrict__ B,
                                                const float* __restrict__ bias,
                                                float* __restrict__ C,
                                                int M, int N, int K) {
    gemm_body<RELU>(A, B, bias, C, M, N, K, blockIdx.y << 6, blockIdx.x << 6);
}

// all layers' K/V projections in one dense launch: grid.z = l*2 + isV
__global__ void __launch_bounds__(256) gemm_kv_all(const float* __restrict__ mem,
                                                   const float* __restrict__ Wk,
                                                   const float* __restrict__ bk,
                                                   const float* __restrict__ Wv,
                                                   const float* __restrict__ bv,
                                                   float* __restrict__ kall,
                                                   float* __restrict__ vall) {
    const int z = blockIdx.z;
    const int l = z >> 1;
    const bool isv = z & 1;
    const float* B    = (isv ? Wv : Wk) + (size_t)l * EE * EE;
    const float* bias = (isv ? bv : bk) + (size_t)l * EE;
    float* C          = (isv ? vall : kall) + (size_t)l * MMEM * EE;
    gemm_body<false>(mem, B, bias, C, MMEM, EE, EE, blockIdx.y << 6, blockIdx.x << 6);
}

// ---------------- tf32 tensor-core flash attention (1-pass tf32) ------------------
#define PAD_Q 36
#define PAD_K 68
#define PAD_V 36
#define PAD_P 68

__global__ void __launch_bounds__(128) flash_tc_kernel(const float* __restrict__ Q,
                                                       const float* __restrict__ Km,
                                                       const float* __restrict__ Vm,
                                                       float* __restrict__ O) {
    const int h  = blockIdx.y;
    const int pb = blockIdx.x << 6;
    __shared__ float Qs[64][PAD_Q];
    __shared__ float Ks[32][PAD_K];
    __shared__ float Vs[64][PAD_V];
    __shared__ float Ps[64][PAD_P];
    const int tid  = threadIdx.x;
    const int warp = tid >> 5, lane = tid & 31;
    const int qd = lane >> 2;
    const int qt = lane & 3;
    const int r0 = (warp << 4) + qd;

    {
        const float alpha = 0.17677669529663687f;
        int idx = tid;
#pragma unroll
        for (int i = 0; i < 4; i++, idx += 128) {
            int row = idx >> 3, c4 = (idx & 7) << 2;
            float4 v = *(const float4*)(Q + (size_t)(pb + row) * EE + h * DH + c4);
            Qs[row][c4 + 0] = v.x * alpha; Qs[row][c4 + 1] = v.y * alpha;
            Qs[row][c4 + 2] = v.z * alpha; Qs[row][c4 + 3] = v.w * alpha;
        }
    }
    float oacc[4][4] = {};
    float lsum0 = 0.f, lsum1 = 0.f;
    __syncthreads();

    for (int mb = 0; mb < MMEM; mb += 64) {
        {
            int idx = tid;
#pragma unroll
            for (int i = 0; i < 4; i++, idx += 128) {
                int m = idx >> 3, c4 = (idx & 7) << 2;
                float4 kv = *(const float4*)(Km + (size_t)(mb + m) * EE + h * DH + c4);
                Ks[c4 + 0][m] = kv.x; Ks[c4 + 1][m] = kv.y;
                Ks[c4 + 2][m] = kv.z; Ks[c4 + 3][m] = kv.w;
                *(float4*)&Vs[m][c4] = *(const float4*)(Vm + (size_t)(mb + m) * EE + h * DH + c4);
            }
        }
        __syncthreads();

        float sacc[8][4] = {};
#pragma unroll
        for (int kk = 0; kk < 4; kk++) {
            uint32_t a0 = __float_as_uint(Qs[r0    ][kk * 8 + qt]);
            uint32_t a1 = __float_as_uint(Qs[r0 + 8][kk * 8 + qt]);
            uint32_t a2 = __float_as_uint(Qs[r0    ][kk * 8 + qt + 4]);
            uint32_t a3 = __float_as_uint(Qs[r0 + 8][kk * 8 + qt + 4]);
#pragma unroll
            for (int j = 0; j < 8; j++) {
                uint32_t b0 = __float_as_uint(Ks[kk * 8 + qt    ][j * 8 + qd]);
                uint32_t b1 = __float_as_uint(Ks[kk * 8 + qt + 4][j * 8 + qd]);
                mma_tf32(sacc[j], a0, a1, a2, a3, b0, b1);
            }
        }

#pragma unroll
        for (int j = 0; j < 8; j++) {
            float e0 = __expf(sacc[j][0]), e1 = __expf(sacc[j][1]);
            float e2 = __expf(sacc[j][2]), e3 = __expf(sacc[j][3]);
            lsum0 += e0 + e1; lsum1 += e2 + e3;
            *(float2*)&Ps[r0    ][j * 8 + (qt << 1)] = make_float2(e0, e1);
            *(float2*)&Ps[r0 + 8][j * 8 + (qt << 1)] = make_float2(e2, e3);
        }
        __syncwarp();

#pragma unroll
        for (int kk = 0; kk < 8; kk++) {
            uint32_t a0 = __float_as_uint(Ps[r0    ][kk * 8 + qt]);
            uint32_t a1 = __float_as_uint(Ps[r0 + 8][kk * 8 + qt]);
            uint32_t a2 = __float_as_uint(Ps[r0    ][kk * 8 + qt + 4]);
            uint32_t a3 = __float_as_uint(Ps[r0 + 8][kk * 8 + qt + 4]);
#pragma unroll
            for (int j = 0; j < 4; j++) {
                uint32_t b0 = __float_as_uint(Vs[kk * 8 + qt    ][j * 8 + qd]);
                uint32_t b1 = __float_as_uint(Vs[kk * 8 + qt + 4][j * 8 + qd]);
                mma_tf32(oacc[j], a0, a1, a2, a3, b0, b1);
            }
        }
        __syncthreads();
    }

    lsum0 += __shfl_xor_sync(0xffffffffu, lsum0, 1);
    lsum0 += __shfl_xor_sync(0xffffffffu, lsum0, 2);
    lsum1 += __shfl_xor_sync(0xffffffffu, lsum1, 1);
    lsum1 += __shfl_xor_sync(0xffffffffu, lsum1, 2);
    float inv0 = 1.0f / lsum0, inv1 = 1.0f / lsum1;
#pragma unroll
    for (int j = 0; j < 4; j++) {
        float* op = O + (size_t)(pb + r0) * EE + h * DH + j * 8 + (qt << 1);
        *(float2*)op            = make_float2(oacc[j][0] * inv0, oacc[j][1] * inv0);
        *(float2*)(op + 8 * EE) = make_float2(oacc[j][2] * inv1, oacc[j][3] * inv1);
    }
}

// q = LayerNorm(q + resid) * g + b
__global__ void add_ln_kernel(float* __restrict__ Qb, const float* __restrict__ R,
                              const float* __restrict__ g, const float* __restrict__ b) {
    const int p = blockIdx.x;
    const int e = threadIdx.x;
    __shared__ float sh[8];
    float x = Qb[(size_t)p * EE + e] + R[(size_t)p * EE + e];
    float s = x;
#pragma unroll
    for (int o = 16; o > 0; o >>= 1) s += __shfl_xor_sync(0xffffffffu, s, o);
    if ((e & 31) == 0) sh[e >> 5] = s;
    __syncthreads();
    float mean = (sh[0] + sh[1] + sh[2] + sh[3] + sh[4] + sh[5] + sh[6] + sh[7]) * (1.0f / 256.0f);
    float d = x - mean;
    __syncthreads();
    s = d * d;
#pragma unroll
    for (int o = 16; o > 0; o >>= 1) s += __shfl_xor_sync(0xffffffffu, s, o);
    if ((e & 31) == 0) sh[e >> 5] = s;
    __syncthreads();
    float var = (sh[0] + sh[1] + sh[2] + sh[3] + sh[4] + sh[5] + sh[6] + sh[7]) * (1.0f / 256.0f);
    Qb[(size_t)p * EE + e] = d * rsqrtf(var + 1e-5f) * g[e] + b[e];
}

__global__ void idx_kernel(const float* __restrict__ refs, int* __restrict__ rows,
                           int* __restrict__ cols, float* __restrict__ rfx,
                           float* __restrict__ rfy) {
    int p = blockIdx.x * blockDim.x + threadIdx.x;
    if (p >= PAIRS) return;
    int r = 0, off = 0;
    while (p >= off + (NQ - 1 - r)) { off += NQ - 1 - r; r++; }
    int c = r + 1 + (p - off);
    rows[p] = r; cols[p] = c;
    rfx[p] = 0.5f * (refs[r * 4 + 0] + refs[c * 4 + 0]);
    rfy[p] = 0.5f * (refs[r * 4 + 1] + refs[c * 4 + 1]);
}

__global__ void pairc_kernel(const float* __restrict__ H, const int* __restrict__ rows,
                             const int* __restrict__ cols, float* __restrict__ PC) {
    const int p = blockIdx.x;
    const int e = threadIdx.x;
    int r = rows[p], c = cols[p];
    PC[(size_t)p * 512 + e]       = H[r * EE + e];
    PC[(size_t)p * 512 + 256 + e] = H[c * EE + e];
}

__global__ void addref_kernel(float* __restrict__ Qb, const float* __restrict__ rfx,
                              const float* __restrict__ rfy, const float* __restrict__ Wref) {
    const int p = blockIdx.x;
    const int e = threadIdx.x;
    Qb[(size_t)p * EE + e] += rfx[p] * Wref[e] + rfy[p] * Wref[EE + e];
}

__global__ void score_kernel(const float* __restrict__ Qb, const float* __restrict__ Tx,
                             const float* __restrict__ lsc, const int* __restrict__ rows,
                             const int* __restrict__ cols, float* __restrict__ out) {
    const int pp = blockIdx.x;
    __shared__ float qr[EE];
    const int tid = threadIdx.x;
    qr[tid] = Qb[(size_t)pp * EE + tid];
    __syncthreads();
    const float scale = expf(lsc[0]);
    const int w = tid >> 5, lane = tid & 31;
    const int r = rows[pp], c = cols[pp];
    for (int t = w; t < TTXT; t += 8) {
        float sum = 0.0f;
#pragma unroll
        for (int i = 0; i < 8; i++)
            sum = fmaf(qr[lane + (i << 5)], Tx[(size_t)t * EE + lane + (i << 5)], sum);
#pragma unroll
        for (int o = 16; o > 0; o >>= 1) sum += __shfl_down_sync(0xffffffffu, sum, o);
        if (lane == 0) {
            float vv = sum * scale;
            out[(size_t)(r * NQ + c) * TTXT + t] = vv;
            out[(size_t)(c * NQ + r) * TTXT + t] = vv;
        }
    }
}

// ----------------------------------- launcher ------------------------------------
extern "C" void kernel_launch(void* const* d_in, const int* in_sizes, int n_in,
                              void* d_out, int out_size) {
    const float* hid    = (const float*)d_in[0];
    const float* memin  = (const float*)d_in[1];
    const float* refs   = (const float*)d_in[2];
    const float* mtext  = (const float*)d_in[3];
    const float* W_pair = (const float*)d_in[6];
    const float* b_pair = (const float*)d_in[7];
    const float* W_mem  = (const float*)d_in[8];
    const float* b_mem  = (const float*)d_in[9];
    const float* W_text = (const float*)d_in[10];
    const float* b_text = (const float*)d_in[11];
    const float* W_ref  = (const float*)d_in[12];
    const float* Wq = (const float*)d_in[13]; const float* bq = (const float*)d_in[14];
    const float* Wk = (const float*)d_in[15]; const float* bk = (const float*)d_in[16];
    const float* Wv = (const float*)d_in[17]; const float* bv = (const float*)d_in[18];
    const float* Wo = (const float*)d_in[19]; const float* bo = (const float*)d_in[20];
    const float* ln1g = (const float*)d_in[21]; const float* ln1b = (const float*)d_in[22];
    const float* ln2g = (const float*)d_in[23]; const float* ln2b = (const float*)d_in[24];
    const float* Wf1 = (const float*)d_in[25]; const float* bf1 = (const float*)d_in[26];
    const float* Wf2 = (const float*)d_in[27]; const float* bf2 = (const float*)d_in[28];
    const float* lsc = (const float*)d_in[29];
    float* out = (float*)d_out;

    float *pc, *q, *qh, *mem, *kall, *vall, *attn, *proj, *ffb, *text, *rfx, *rfy;
    int *rowp, *colp;
    cudaGetSymbolAddress((void**)&pc,   g_pairconcat);
    cudaGetSymbolAddress((void**)&q,    g_q);
    cudaGetSymbolAddress((void**)&qh,   g_qh);
    cudaGetSymbolAddress((void**)&mem,  g_mem);
    cudaGetSymbolAddress((void**)&kall, g_kall);
    cudaGetSymbolAddress((void**)&vall, g_vall);
    cudaGetSymbolAddress((void**)&attn, g_attn);
    cudaGetSymbolAddress((void**)&proj, g_proj);
    cudaGetSymbolAddress((void**)&ffb,  g_ffb);
    cudaGetSymbolAddress((void**)&text, g_text);
    cudaGetSymbolAddress((void**)&rowp, g_rowi);
    cudaGetSymbolAddress((void**)&colp, g_coli);
    cudaGetSymbolAddress((void**)&rfx,  g_refx);
    cudaGetSymbolAddress((void**)&rfy,  g_refy);

    idx_kernel<<<8, 256>>>(refs, rowp, colp, rfx, rfy);
    pairc_kernel<<<PAIRS, 256>>>(hid, rowp, colp, pc);
    gemm_tc3<false><<<dim3(4, 32), 256>>>(pc, W_pair, b_pair, q, PAIRS, EE, 512);
    addref_kernel<<<PAIRS, 256>>>(q, rfx, rfy, W_ref);
    gemm_tc3<false><<<dim3(4, 64), 256>>>(memin, W_mem, b_mem, mem, MMEM, EE, EE);
    gemm_tc3<false><<<dim3(4, 1), 256>>>(mtext, W_text, b_text, text, TTXT, EE, EE);
    // all layers' K/V projections in one dense launch (2048 blocks)
    gemm_kv_all<<<dim3(4, 64, 2 * LLAYERS), 256>>>(mem, Wk, bk, Wv, bv, kall, vall);

    for (int l = 0; l < LLAYERS; l++) {
        gemm_tc3<false><<<dim3(4, 32), 256>>>(q, Wq + (size_t)l * EE * EE, bq + l * EE, qh, PAIRS, EE, EE);
        flash_tc_kernel<<<dim3(PPAD / 64, HN), 128>>>(qh, kall + (size_t)l * MMEM * EE,
                                                      vall + (size_t)l * MMEM * EE, attn);
        gemm_tc3<false><<<dim3(4, 32), 256>>>(attn, Wo + (size_t)l * EE * EE, bo + l * EE, proj, PAIRS, EE, EE);
        add_ln_kernel<<<PAIRS, 256>>>(q, proj, ln1g + l * EE, ln1b + l * EE);
        gemm_tc3<true ><<<dim3(16, 32), 256>>>(q, Wf1 + (size_t)l * EE * FFD, bf1 + l * FFD, ffb, PAIRS, FFD, EE);
        gemm_tc3<false><<<dim3(4, 32), 256>>>(ffb, Wf2 + (size_t)l * FFD * EE, bf2 + l * EE, proj, PAIRS, EE, FFD);
        add_ln_kernel<<<PAIRS, 256>>>(q, proj, ln2g + l * EE, ln2b + l * EE);
    }

    cudaMemsetAsync(d_out, 0, (size_t)out_size * sizeof(float), 0);
    score_kernel<<<PAIRS, 256>>>(q, text, lsc, rowp, colp, out);
}

// round 7
// speedup vs baseline: 1.3279x; 1.3216x over previous
#include <cuda_runtime.h>
#include <cstdint>

#define EE 256
#define HN 8
#define DH 32
#define LLAYERS 4
#define FFD 1024
#define NQ 64
#define PAIRS 2016
#define PPAD 2048
#define MMEM 4096
#define TTXT 32

// ---------------- scratch (static device globals; allocation-free) ----------------
__device__ float g_pairconcat[PPAD * 512];
__device__ float g_q[PPAD * EE];
__device__ float g_qh[PPAD * EE];
__device__ float g_mem[MMEM * EE];
__device__ float g_kall[LLAYERS * MMEM * EE];
__device__ float g_vall[LLAYERS * MMEM * EE];
__device__ float g_attn[PPAD * EE];
__device__ float g_proj[PPAD * EE];
__device__ float g_ffb[PPAD * FFD];
__device__ float g_text[TTXT * EE];
__device__ int   g_rowi[PAIRS];
__device__ int   g_coli[PAIRS];
__device__ float g_refx[PAIRS];
__device__ float g_refy[PAIRS];

__device__ __forceinline__ void mma_tf32(float* c, uint32_t a0, uint32_t a1,
                                         uint32_t a2, uint32_t a3,
                                         uint32_t b0, uint32_t b1) {
    asm volatile(
        "mma.sync.aligned.m16n8k8.row.col.f32.tf32.tf32.f32 "
        "{%0,%1,%2,%3}, {%4,%5,%6,%7}, {%8,%9}, {%0,%1,%2,%3};\n"
        : "+f"(c[0]), "+f"(c[1]), "+f"(c[2]), "+f"(c[3])
        : "r"(a0), "r"(a1), "r"(a2), "r"(a3), "r"(b0), "r"(b1));
}

__device__ __forceinline__ void mma_bf16(float* c, uint32_t a0, uint32_t a1,
                                         uint32_t a2, uint32_t a3,
                                         uint32_t b0, uint32_t b1) {
    asm volatile(
        "mma.sync.aligned.m16n8k16.row.col.f32.bf16.bf16.f32 "
        "{%0,%1,%2,%3}, {%4,%5,%6,%7}, {%8,%9}, {%0,%1,%2,%3};\n"
        : "+f"(c[0]), "+f"(c[1]), "+f"(c[2]), "+f"(c[3])
        : "r"(a0), "r"(a1), "r"(a2), "r"(a3), "r"(b0), "r"(b1));
}

// pack two floats to bf16x2: even-k element -> low half, odd-k -> high half
__device__ __forceinline__ uint32_t pack_bf2(float e_lo, float e_hi) {
    uint32_t r;
    asm("cvt.rn.bf16x2.f32 %0, %1, %2;" : "=r"(r) : "f"(e_hi), "f"(e_lo));
    return r;
}
__device__ __forceinline__ float bf_lo(uint32_t p) { return __uint_as_float(p << 16); }
__device__ __forceinline__ float bf_hi(uint32_t p) { return __uint_as_float(p & 0xffff0000u); }

// ---------------- bf16x2 3-product GEMM: C = A[M,K]@B[K,N] + bias (opt ReLU) ------
// block 64x64, BK=32, 128 thr (4 warps), warp tile 32x32 (2 row-groups x 4 n-cols).
#define APAD 18
#define BPAD 68
template <bool RELU>
__device__ __forceinline__ void gemm_body(const float* __restrict__ A,
                                          const float* __restrict__ B,
                                          const float* __restrict__ bias,
                                          float* __restrict__ C,
                                          int M, int N, int K, int bm, int bn) {
    __shared__ uint32_t As1[64][APAD], As2[64][APAD];   // [row][k2]  (k2 = k/2)
    __shared__ uint32_t Bs1[16][BPAD], Bs2[16][BPAD];   // [k2][n]
    const int tid  = threadIdx.x;
    const int warp = tid >> 5, lane = tid & 31;
    const int qd = lane >> 2, qt = lane & 3;
    const int rbase = (warp >> 1) << 5;   // 0 or 32
    const int cbase = (warp & 1) << 5;    // 0 or 32

    // A: 4 float4 per thread (64 rows x 8 quads); B: 2 row-pair float4 loads
    int arw[4], akq[4], bk2[2], bn4[2];
#pragma unroll
    for (int i = 0; i < 4; i++) {
        int idx = tid + (i << 7);
        arw[i] = idx >> 3; akq[i] = idx & 7;
    }
#pragma unroll
    for (int i = 0; i < 2; i++) {
        int idx = tid + (i << 7);
        bk2[i] = idx >> 4; bn4[i] = (idx & 15) << 2;
    }
    float4 rA[4]; float4 rB0[2], rB1[2];
#pragma unroll
    for (int i = 0; i < 4; i++) {
        int gr = bm + arw[i]; if (gr >= M) gr = M - 1;
        rA[i] = *(const float4*)(A + (size_t)gr * K + (akq[i] << 2));
    }
#pragma unroll
    for (int i = 0; i < 2; i++) {
        rB0[i] = *(const float4*)(B + (size_t)(2 * bk2[i])     * N + bn + bn4[i]);
        rB1[i] = *(const float4*)(B + (size_t)(2 * bk2[i] + 1) * N + bn + bn4[i]);
    }

    float acc[2][4][4] = {};
    for (int k0 = 0; k0 < K; k0 += 32) {
        // ---- split + pack into smem ----
#pragma unroll
        for (int i = 0; i < 4; i++) {
            int c2 = akq[i] << 1;
            uint32_t h0 = pack_bf2(rA[i].x, rA[i].y);
            uint32_t h1 = pack_bf2(rA[i].z, rA[i].w);
            As1[arw[i]][c2]     = h0;
            As1[arw[i]][c2 + 1] = h1;
            As2[arw[i]][c2]     = pack_bf2(rA[i].x - bf_lo(h0), rA[i].y - bf_hi(h0));
            As2[arw[i]][c2 + 1] = pack_bf2(rA[i].z - bf_lo(h1), rA[i].w - bf_hi(h1));
        }
#pragma unroll
        for (int i = 0; i < 2; i++) {
            float e0[4] = {rB0[i].x, rB0[i].y, rB0[i].z, rB0[i].w};
            float e1[4] = {rB1[i].x, rB1[i].y, rB1[i].z, rB1[i].w};
#pragma unroll
            for (int u = 0; u < 4; u++) {
                uint32_t h = pack_bf2(e0[u], e1[u]);
                Bs1[bk2[i]][bn4[i] + u] = h;
                Bs2[bk2[i]][bn4[i] + u] = pack_bf2(e0[u] - bf_lo(h), e1[u] - bf_hi(h));
            }
        }
        __syncthreads();
        // prefetch next tile
        if (k0 + 32 < K) {
#pragma unroll
            for (int i = 0; i < 4; i++) {
                int gr = bm + arw[i]; if (gr >= M) gr = M - 1;
                rA[i] = *(const float4*)(A + (size_t)gr * K + k0 + 32 + (akq[i] << 2));
            }
#pragma unroll
            for (int i = 0; i < 2; i++) {
                rB0[i] = *(const float4*)(B + (size_t)(k0 + 32 + 2 * bk2[i])     * N + bn + bn4[i]);
                rB1[i] = *(const float4*)(B + (size_t)(k0 + 32 + 2 * bk2[i] + 1) * N + bn + bn4[i]);
            }
        }
        // ---- compute: 2 k16 steps ----
#pragma unroll
        for (int s = 0; s < 2; s++) {
            uint32_t A1[2][4], A2[2][4];
#pragma unroll
            for (int rg = 0; rg < 2; rg++) {
                int r = rbase + (rg << 4);
                A1[rg][0] = As1[r + qd    ][s * 8 + qt];
                A1[rg][1] = As1[r + qd + 8][s * 8 + qt];
                A1[rg][2] = As1[r + qd    ][s * 8 + qt + 4];
                A1[rg][3] = As1[r + qd + 8][s * 8 + qt + 4];
                A2[rg][0] = As2[r + qd    ][s * 8 + qt];
                A2[rg][1] = As2[r + qd + 8][s * 8 + qt];
                A2[rg][2] = As2[r + qd    ][s * 8 + qt + 4];
                A2[rg][3] = As2[r + qd + 8][s * 8 + qt + 4];
            }
#pragma unroll
            for (int j = 0; j < 4; j++) {
                int col = cbase + j * 8 + qd;
                uint32_t b10 = Bs1[s * 8 + qt    ][col];
                uint32_t b11 = Bs1[s * 8 + qt + 4][col];
                uint32_t b20 = Bs2[s * 8 + qt    ][col];
                uint32_t b21 = Bs2[s * 8 + qt + 4][col];
#pragma unroll
                for (int rg = 0; rg < 2; rg++) {
                    mma_bf16(acc[rg][j], A1[rg][0], A1[rg][1], A1[rg][2], A1[rg][3], b20, b21);
                    mma_bf16(acc[rg][j], A2[rg][0], A2[rg][1], A2[rg][2], A2[rg][3], b10, b11);
                    mma_bf16(acc[rg][j], A1[rg][0], A1[rg][1], A1[rg][2], A1[rg][3], b10, b11);
                }
            }
        }
        __syncthreads();
    }
#pragma unroll
    for (int rg = 0; rg < 2; rg++) {
        int ra0 = bm + rbase + (rg << 4) + qd, ra1 = ra0 + 8;
#pragma unroll
        for (int j = 0; j < 4; j++) {
            int col = bn + cbase + j * 8 + (qt << 1);
            float b0 = bias[col], b1 = bias[col + 1];
            if (ra0 < M) {
                float v0 = acc[rg][j][0] + b0, v1 = acc[rg][j][1] + b1;
                if (RELU) { v0 = fmaxf(v0, 0.f); v1 = fmaxf(v1, 0.f); }
                *(float2*)(C + (size_t)ra0 * N + col) = make_float2(v0, v1);
            }
            if (ra1 < M) {
                float v2 = acc[rg][j][2] + b0, v3 = acc[rg][j][3] + b1;
                if (RELU) { v2 = fmaxf(v2, 0.f); v3 = fmaxf(v3, 0.f); }
                *(float2*)(C + (size_t)ra1 * N + col) = make_float2(v2, v3);
            }
        }
    }
}

template <bool RELU>
__global__ void __launch_bounds__(128) gemm_bf(const float* __restrict__ A,
                                               const float* __restrict__ B,
                                               const float* __restrict__ bias,
                                               float* __restrict__ C,
                                               int M, int N, int K) {
    gemm_body<RELU>(A, B, bias, C, M, N, K, blockIdx.y << 6, blockIdx.x << 6);
}

// all layers' K/V projections: grid.z = l*2 + isV
__global__ void __launch_bounds__(128) gemm_kv_all(const float* __restrict__ mem,
                                                   const float* __restrict__ Wk,
                                                   const float* __restrict__ bk,
                                                   const float* __restrict__ Wv,
                                                   const float* __restrict__ bv,
                                                   float* __restrict__ kall,
                                                   float* __restrict__ vall) {
    const int z = blockIdx.z;
    const int l = z >> 1;
    const bool isv = z & 1;
    const float* B    = (isv ? Wv : Wk) + (size_t)l * EE * EE;
    const float* bias = (isv ? bv : bk) + (size_t)l * EE;
    float* C          = (isv ? vall : kall) + (size_t)l * MMEM * EE;
    gemm_body<false>(mem, B, bias, C, MMEM, EE, EE, blockIdx.y << 6, blockIdx.x << 6);
}

// ---------------- tf32 tensor-core flash attention (1-pass tf32) ------------------
#define PAD_Q 36
#define PAD_K 68
#define PAD_V 36
#define PAD_P 68

__global__ void __launch_bounds__(128) flash_tc_kernel(const float* __restrict__ Q,
                                                       const float* __restrict__ Km,
                                                       const float* __restrict__ Vm,
                                                       float* __restrict__ O) {
    const int h  = blockIdx.y;
    const int pb = blockIdx.x << 6;
    __shared__ float Qs[64][PAD_Q];
    __shared__ float Ks[32][PAD_K];
    __shared__ float Vs[64][PAD_V];
    __shared__ float Ps[64][PAD_P];
    const int tid  = threadIdx.x;
    const int warp = tid >> 5, lane = tid & 31;
    const int qd = lane >> 2;
    const int qt = lane & 3;
    const int r0 = (warp << 4) + qd;

    {
        const float alpha = 0.17677669529663687f;
        int idx = tid;
#pragma unroll
        for (int i = 0; i < 4; i++, idx += 128) {
            int row = idx >> 3, c4 = (idx & 7) << 2;
            float4 v = *(const float4*)(Q + (size_t)(pb + row) * EE + h * DH + c4);
            Qs[row][c4 + 0] = v.x * alpha; Qs[row][c4 + 1] = v.y * alpha;
            Qs[row][c4 + 2] = v.z * alpha; Qs[row][c4 + 3] = v.w * alpha;
        }
    }
    float oacc[4][4] = {};
    float lsum0 = 0.f, lsum1 = 0.f;
    __syncthreads();

    for (int mb = 0; mb < MMEM; mb += 64) {
        {
            int idx = tid;
#pragma unroll
            for (int i = 0; i < 4; i++, idx += 128) {
                int m = idx >> 3, c4 = (idx & 7) << 2;
                float4 kv = *(const float4*)(Km + (size_t)(mb + m) * EE + h * DH + c4);
                Ks[c4 + 0][m] = kv.x; Ks[c4 + 1][m] = kv.y;
                Ks[c4 + 2][m] = kv.z; Ks[c4 + 3][m] = kv.w;
                *(float4*)&Vs[m][c4] = *(const float4*)(Vm + (size_t)(mb + m) * EE + h * DH + c4);
            }
        }
        __syncthreads();

        float sacc[8][4] = {};
#pragma unroll
        for (int kk = 0; kk < 4; kk++) {
            uint32_t a0 = __float_as_uint(Qs[r0    ][kk * 8 + qt]);
            uint32_t a1 = __float_as_uint(Qs[r0 + 8][kk * 8 + qt]);
            uint32_t a2 = __float_as_uint(Qs[r0    ][kk * 8 + qt + 4]);
            uint32_t a3 = __float_as_uint(Qs[r0 + 8][kk * 8 + qt + 4]);
#pragma unroll
            for (int j = 0; j < 8; j++) {
                uint32_t b0 = __float_as_uint(Ks[kk * 8 + qt    ][j * 8 + qd]);
                uint32_t b1 = __float_as_uint(Ks[kk * 8 + qt + 4][j * 8 + qd]);
                mma_tf32(sacc[j], a0, a1, a2, a3, b0, b1);
            }
        }

#pragma unroll
        for (int j = 0; j < 8; j++) {
            float e0 = __expf(sacc[j][0]), e1 = __expf(sacc[j][1]);
            float e2 = __expf(sacc[j][2]), e3 = __expf(sacc[j][3]);
            lsum0 += e0 + e1; lsum1 += e2 + e3;
            *(float2*)&Ps[r0    ][j * 8 + (qt << 1)] = make_float2(e0, e1);
            *(float2*)&Ps[r0 + 8][j * 8 + (qt << 1)] = make_float2(e2, e3);
        }
        __syncwarp();

#pragma unroll
        for (int kk = 0; kk < 8; kk++) {
            uint32_t a0 = __float_as_uint(Ps[r0    ][kk * 8 + qt]);
            uint32_t a1 = __float_as_uint(Ps[r0 + 8][kk * 8 + qt]);
            uint32_t a2 = __float_as_uint(Ps[r0    ][kk * 8 + qt + 4]);
            uint32_t a3 = __float_as_uint(Ps[r0 + 8][kk * 8 + qt + 4]);
#pragma unroll
            for (int j = 0; j < 4; j++) {
                uint32_t b0 = __float_as_uint(Vs[kk * 8 + qt    ][j * 8 + qd]);
                uint32_t b1 = __float_as_uint(Vs[kk * 8 + qt + 4][j * 8 + qd]);
                mma_tf32(oacc[j], a0, a1, a2, a3, b0, b1);
            }
        }
        __syncthreads();
    }

    lsum0 += __shfl_xor_sync(0xffffffffu, lsum0, 1);
    lsum0 += __shfl_xor_sync(0xffffffffu, lsum0, 2);
    lsum1 += __shfl_xor_sync(0xffffffffu, lsum1, 1);
    lsum1 += __shfl_xor_sync(0xffffffffu, lsum1, 2);
    float inv0 = 1.0f / lsum0, inv1 = 1.0f / lsum1;
#pragma unroll
    for (int j = 0; j < 4; j++) {
        float* op = O + (size_t)(pb + r0) * EE + h * DH + j * 8 + (qt << 1);
        *(float2*)op            = make_float2(oacc[j][0] * inv0, oacc[j][1] * inv0);
        *(float2*)(op + 8 * EE) = make_float2(oacc[j][2] * inv1, oacc[j][3] * inv1);
    }
}

// q = LayerNorm(q + resid) * g + b
__global__ void add_ln_kernel(float* __restrict__ Qb, const float* __restrict__ R,
                              const float* __restrict__ g, const float* __restrict__ b) {
    const int p = blockIdx.x;
    const int e = threadIdx.x;
    __shared__ float sh[8];
    float x = Qb[(size_t)p * EE + e] + R[(size_t)p * EE + e];
    float s = x;
#pragma unroll
    for (int o = 16; o > 0; o >>= 1) s += __shfl_xor_sync(0xffffffffu, s, o);
    if ((e & 31) == 0) sh[e >> 5] = s;
    __syncthreads();
    float mean = (sh[0] + sh[1] + sh[2] + sh[3] + sh[4] + sh[5] + sh[6] + sh[7]) * (1.0f / 256.0f);
    float d = x - mean;
    __syncthreads();
    s = d * d;
#pragma unroll
    for (int o = 16; o > 0; o >>= 1) s += __shfl_xor_sync(0xffffffffu, s, o);
    if ((e & 31) == 0) sh[e >> 5] = s;
    __syncthreads();
    float var = (sh[0] + sh[1] + sh[2] + sh[3] + sh[4] + sh[5] + sh[6] + sh[7]) * (1.0f / 256.0f);
    Qb[(size_t)p * EE + e] = d * rsqrtf(var + 1e-5f) * g[e] + b[e];
}

__global__ void idx_kernel(const float* __restrict__ refs, int* __restrict__ rows,
                           int* __restrict__ cols, float* __restrict__ rfx,
                           float* __restrict__ rfy) {
    int p = blockIdx.x * blockDim.x + threadIdx.x;
    if (p >= PAIRS) return;
    int r = 0, off = 0;
    while (p >= off + (NQ - 1 - r)) { off += NQ - 1 - r; r++; }
    int c = r + 1 + (p - off);
    rows[p] = r; cols[p] = c;
    rfx[p] = 0.5f * (refs[r * 4 + 0] + refs[c * 4 + 0]);
    rfy[p] = 0.5f * (refs[r * 4 + 1] + refs[c * 4 + 1]);
}

__global__ void pairc_kernel(const float* __restrict__ H, const int* __restrict__ rows,
                             const int* __restrict__ cols, float* __restrict__ PC) {
    const int p = blockIdx.x;
    const int e = threadIdx.x;
    int r = rows[p], c = cols[p];
    PC[(size_t)p * 512 + e]       = H[r * EE + e];
    PC[(size_t)p * 512 + 256 + e] = H[c * EE + e];
}

__global__ void addref_kernel(float* __restrict__ Qb, const float* __restrict__ rfx,
                              const float* __restrict__ rfy, const float* __restrict__ Wref) {
    const int p = blockIdx.x;
    const int e = threadIdx.x;
    Qb[(size_t)p * EE + e] += rfx[p] * Wref[e] + rfy[p] * Wref[EE + e];
}

__global__ void score_kernel(const float* __restrict__ Qb, const float* __restrict__ Tx,
                             const float* __restrict__ lsc, const int* __restrict__ rows,
                             const int* __restrict__ cols, float* __restrict__ out) {
    const int pp = blockIdx.x;
    __shared__ float qr[EE];
    const int tid = threadIdx.x;
    qr[tid] = Qb[(size_t)pp * EE + tid];
    __syncthreads();
    const float scale = expf(lsc[0]);
    const int w = tid >> 5, lane = tid & 31;
    const int r = rows[pp], c = cols[pp];
    for (int t = w; t < TTXT; t += 8) {
        float sum = 0.0f;
#pragma unroll
        for (int i = 0; i < 8; i++)
            sum = fmaf(qr[lane + (i << 5)], Tx[(size_t)t * EE + lane + (i << 5)], sum);
#pragma unroll
        for (int o = 16; o > 0; o >>= 1) sum += __shfl_down_sync(0xffffffffu, sum, o);
        if (lane == 0) {
            float vv = sum * scale;
            out[(size_t)(r * NQ + c) * TTXT + t] = vv;
            out[(size_t)(c * NQ + r) * TTXT + t] = vv;
        }
    }
}

// ----------------------------------- launcher ------------------------------------
extern "C" void kernel_launch(void* const* d_in, const int* in_sizes, int n_in,
                              void* d_out, int out_size) {
    const float* hid    = (const float*)d_in[0];
    const float* memin  = (const float*)d_in[1];
    const float* refs   = (const float*)d_in[2];
    const float* mtext  = (const float*)d_in[3];
    const float* W_pair = (const float*)d_in[6];
    const float* b_pair = (const float*)d_in[7];
    const float* W_mem  = (const float*)d_in[8];
    const float* b_mem  = (const float*)d_in[9];
    const float* W_text = (const float*)d_in[10];
    const float* b_text = (const float*)d_in[11];
    const float* W_ref  = (const float*)d_in[12];
    const float* Wq = (const float*)d_in[13]; const float* bq = (const float*)d_in[14];
    const float* Wk = (const float*)d_in[15]; const float* bk = (const float*)d_in[16];
    const float* Wv = (const float*)d_in[17]; const float* bv = (const float*)d_in[18];
    const float* Wo = (const float*)d_in[19]; const float* bo = (const float*)d_in[20];
    const float* ln1g = (const float*)d_in[21]; const float* ln1b = (const float*)d_in[22];
    const float* ln2g = (const float*)d_in[23]; const float* ln2b = (const float*)d_in[24];
    const float* Wf1 = (const float*)d_in[25]; const float* bf1 = (const float*)d_in[26];
    const float* Wf2 = (const float*)d_in[27]; const float* bf2 = (const float*)d_in[28];
    const float* lsc = (const float*)d_in[29];
    float* out = (float*)d_out;

    float *pc, *q, *qh, *mem, *kall, *vall, *attn, *proj, *ffb, *text, *rfx, *rfy;
    int *rowp, *colp;
    cudaGetSymbolAddress((void**)&pc,   g_pairconcat);
    cudaGetSymbolAddress((void**)&q,    g_q);
    cudaGetSymbolAddress((void**)&qh,   g_qh);
    cudaGetSymbolAddress((void**)&mem,  g_mem);
    cudaGetSymbolAddress((void**)&kall, g_kall);
    cudaGetSymbolAddress((void**)&vall, g_vall);
    cudaGetSymbolAddress((void**)&attn, g_attn);
    cudaGetSymbolAddress((void**)&proj, g_proj);
    cudaGetSymbolAddress((void**)&ffb,  g_ffb);
    cudaGetSymbolAddress((void**)&text, g_text);
    cudaGetSymbolAddress((void**)&rowp, g_rowi);
    cudaGetSymbolAddress((void**)&colp, g_coli);
    cudaGetSymbolAddress((void**)&rfx,  g_refx);
    cudaGetSymbolAddress((void**)&rfy,  g_refy);

    idx_kernel<<<8, 256>>>(refs, rowp, colp, rfx, rfy);
    pairc_kernel<<<PAIRS, 256>>>(hid, rowp, colp, pc);
    gemm_bf<false><<<dim3(4, 32), 128>>>(pc, W_pair, b_pair, q, PAIRS, EE, 512);
    addref_kernel<<<PAIRS, 256>>>(q, rfx, rfy, W_ref);
    gemm_bf<false><<<dim3(4, 64), 128>>>(memin, W_mem, b_mem, mem, MMEM, EE, EE);
    gemm_bf<false><<<dim3(4, 1), 128>>>(mtext, W_text, b_text, text, TTXT, EE, EE);
    gemm_kv_all<<<dim3(4, 64, 2 * LLAYERS), 128>>>(mem, Wk, bk, Wv, bv, kall, vall);

    for (int l = 0; l < LLAYERS; l++) {
        gemm_bf<false><<<dim3(4, 32), 128>>>(q, Wq + (size_t)l * EE * EE, bq + l * EE, qh, PAIRS, EE, EE);
        flash_tc_kernel<<<dim3(PPAD / 64, HN), 128>>>(qh, kall + (size_t)l * MMEM * EE,
                                                      vall + (size_t)l * MMEM * EE, attn);
        gemm_bf<false><<<dim3(4, 32), 128>>>(attn, Wo + (size_t)l * EE * EE, bo + l * EE, proj, PAIRS, EE, EE);
        add_ln_kernel<<<PAIRS, 256>>>(q, proj, ln1g + l * EE, ln1b + l * EE);
        gemm_bf<true ><<<dim3(16, 32), 128>>>(q, Wf1 + (size_t)l * EE * FFD, bf1 + l * FFD, ffb, PAIRS, FFD, EE);
        gemm_bf<false><<<dim3(4, 32), 128>>>(ffb, Wf2 + (size_t)l * FFD * EE, bf2 + l * EE, proj, PAIRS, EE, FFD);
        add_ln_kernel<<<PAIRS, 256>>>(q, proj, ln2g + l * EE, ln2b + l * EE);
    }

    cudaMemsetAsync(d_out, 0, (size_t)out_size * sizeof(float), 0);
    score_kernel<<<PAIRS, 256>>>(q, text, lsc, rowp, colp, out);
}

// round 8
// speedup vs baseline: 1.7401x; 1.3104x over previous
#include <cuda_runtime.h>
#include <cstdint>

#define EE 256
#define HN 8
#define DH 32
#define LLAYERS 4
#define FFD 1024
#define NQ 64
#define PAIRS 2016
#define PPAD 2048
#define MMEM 4096
#define TTXT 32

// ---------------- scratch (static device globals; allocation-free) ----------------
__device__ float g_pairconcat[PPAD * 512];
__device__ float g_q[PPAD * EE];
__device__ float g_qh[PPAD * EE];
__device__ float g_mem[MMEM * EE];
__device__ float g_kall[LLAYERS * MMEM * EE];
__device__ float g_vall[LLAYERS * MMEM * EE];
__device__ float g_attn[PPAD * EE];
__device__ float g_proj[PPAD * EE];
__device__ float g_ffb[PPAD * FFD];
__device__ float g_text[TTXT * EE];
__device__ int   g_rowi[PAIRS];
__device__ int   g_coli[PAIRS];
__device__ float g_refx[PAIRS];
__device__ float g_refy[PAIRS];

__device__ __forceinline__ void mma_bf16(float* c, uint32_t a0, uint32_t a1,
                                         uint32_t a2, uint32_t a3,
                                         uint32_t b0, uint32_t b1) {
    asm volatile(
        "mma.sync.aligned.m16n8k16.row.col.f32.bf16.bf16.f32 "
        "{%0,%1,%2,%3}, {%4,%5,%6,%7}, {%8,%9}, {%0,%1,%2,%3};\n"
        : "+f"(c[0]), "+f"(c[1]), "+f"(c[2]), "+f"(c[3])
        : "r"(a0), "r"(a1), "r"(a2), "r"(a3), "r"(b0), "r"(b1));
}

// pack two floats to bf16x2 (first arg -> low half = even k, second -> high = odd k)
__device__ __forceinline__ uint32_t pack_bf2(float e_lo, float e_hi) {
    uint32_t r;
    asm("cvt.rn.bf16x2.f32 %0, %1, %2;" : "=r"(r) : "f"(e_hi), "f"(e_lo));
    return r;
}
__device__ __forceinline__ float bf_lo(uint32_t p) { return __uint_as_float(p << 16); }
__device__ __forceinline__ float bf_hi(uint32_t p) { return __uint_as_float(p & 0xffff0000u); }

// ---------------- bf16x2 3-product GEMM: C = A[M,K]@B[K,N] + bias (opt ReLU) ------
// block 64x64, BK=32, 128 thr (4 warps), warp tile 32x32.
#define APAD 18
#define BPAD 68
template <bool RELU>
__device__ __forceinline__ void gemm_body(const float* __restrict__ A,
                                          const float* __restrict__ B,
                                          const float* __restrict__ bias,
                                          float* __restrict__ C,
                                          int M, int N, int K, int bm, int bn) {
    __shared__ uint32_t As1[64][APAD], As2[64][APAD];
    __shared__ uint32_t Bs1[16][BPAD], Bs2[16][BPAD];
    const int tid  = threadIdx.x;
    const int warp = tid >> 5, lane = tid & 31;
    const int qd = lane >> 2, qt = lane & 3;
    const int rbase = (warp >> 1) << 5;
    const int cbase = (warp & 1) << 5;

    int arw[4], akq[4], bk2[2], bn4[2];
#pragma unroll
    for (int i = 0; i < 4; i++) {
        int idx = tid + (i << 7);
        arw[i] = idx >> 3; akq[i] = idx & 7;
    }
#pragma unroll
    for (int i = 0; i < 2; i++) {
        int idx = tid + (i << 7);
        bk2[i] = idx >> 4; bn4[i] = (idx & 15) << 2;
    }
    float4 rA[4]; float4 rB0[2], rB1[2];
#pragma unroll
    for (int i = 0; i < 4; i++) {
        int gr = bm + arw[i]; if (gr >= M) gr = M - 1;
        rA[i] = *(const float4*)(A + (size_t)gr * K + (akq[i] << 2));
    }
#pragma unroll
    for (int i = 0; i < 2; i++) {
        rB0[i] = *(const float4*)(B + (size_t)(2 * bk2[i])     * N + bn + bn4[i]);
        rB1[i] = *(const float4*)(B + (size_t)(2 * bk2[i] + 1) * N + bn + bn4[i]);
    }

    float acc[2][4][4] = {};
    for (int k0 = 0; k0 < K; k0 += 32) {
#pragma unroll
        for (int i = 0; i < 4; i++) {
            int c2 = akq[i] << 1;
            uint32_t h0 = pack_bf2(rA[i].x, rA[i].y);
            uint32_t h1 = pack_bf2(rA[i].z, rA[i].w);
            As1[arw[i]][c2]     = h0;
            As1[arw[i]][c2 + 1] = h1;
            As2[arw[i]][c2]     = pack_bf2(rA[i].x - bf_lo(h0), rA[i].y - bf_hi(h0));
            As2[arw[i]][c2 + 1] = pack_bf2(rA[i].z - bf_lo(h1), rA[i].w - bf_hi(h1));
        }
#pragma unroll
        for (int i = 0; i < 2; i++) {
            float e0[4] = {rB0[i].x, rB0[i].y, rB0[i].z, rB0[i].w};
            float e1[4] = {rB1[i].x, rB1[i].y, rB1[i].z, rB1[i].w};
#pragma unroll
            for (int u = 0; u < 4; u++) {
                uint32_t h = pack_bf2(e0[u], e1[u]);
                Bs1[bk2[i]][bn4[i] + u] = h;
                Bs2[bk2[i]][bn4[i] + u] = pack_bf2(e0[u] - bf_lo(h), e1[u] - bf_hi(h));
            }
        }
        __syncthreads();
        if (k0 + 32 < K) {
#pragma unroll
            for (int i = 0; i < 4; i++) {
                int gr = bm + arw[i]; if (gr >= M) gr = M - 1;
                rA[i] = *(const float4*)(A + (size_t)gr * K + k0 + 32 + (akq[i] << 2));
            }
#pragma unroll
            for (int i = 0; i < 2; i++) {
                rB0[i] = *(const float4*)(B + (size_t)(k0 + 32 + 2 * bk2[i])     * N + bn + bn4[i]);
                rB1[i] = *(const float4*)(B + (size_t)(k0 + 32 + 2 * bk2[i] + 1) * N + bn + bn4[i]);
            }
        }
#pragma unroll
        for (int s = 0; s < 2; s++) {
            uint32_t A1[2][4], A2[2][4];
#pragma unroll
            for (int rg = 0; rg < 2; rg++) {
                int r = rbase + (rg << 4);
                A1[rg][0] = As1[r + qd    ][s * 8 + qt];
                A1[rg][1] = As1[r + qd + 8][s * 8 + qt];
                A1[rg][2] = As1[r + qd    ][s * 8 + qt + 4];
                A1[rg][3] = As1[r + qd + 8][s * 8 + qt + 4];
                A2[rg][0] = As2[r + qd    ][s * 8 + qt];
                A2[rg][1] = As2[r + qd + 8][s * 8 + qt];
                A2[rg][2] = As2[r + qd    ][s * 8 + qt + 4];
                A2[rg][3] = As2[r + qd + 8][s * 8 + qt + 4];
            }
#pragma unroll
            for (int j = 0; j < 4; j++) {
                int col = cbase + j * 8 + qd;
                uint32_t b10 = Bs1[s * 8 + qt    ][col];
                uint32_t b11 = Bs1[s * 8 + qt + 4][col];
                uint32_t b20 = Bs2[s * 8 + qt    ][col];
                uint32_t b21 = Bs2[s * 8 + qt + 4][col];
#pragma unroll
                for (int rg = 0; rg < 2; rg++) {
                    mma_bf16(acc[rg][j], A1[rg][0], A1[rg][1], A1[rg][2], A1[rg][3], b20, b21);
                    mma_bf16(acc[rg][j], A2[rg][0], A2[rg][1], A2[rg][2], A2[rg][3], b10, b11);
                    mma_bf16(acc[rg][j], A1[rg][0], A1[rg][1], A1[rg][2], A1[rg][3], b10, b11);
                }
            }
        }
        __syncthreads();
    }
#pragma unroll
    for (int rg = 0; rg < 2; rg++) {
        int ra0 = bm + rbase + (rg << 4) + qd, ra1 = ra0 + 8;
#pragma unroll
        for (int j = 0; j < 4; j++) {
            int col = bn + cbase + j * 8 + (qt << 1);
            float b0 = bias[col], b1 = bias[col + 1];
            if (ra0 < M) {
                float v0 = acc[rg][j][0] + b0, v1 = acc[rg][j][1] + b1;
                if (RELU) { v0 = fmaxf(v0, 0.f); v1 = fmaxf(v1, 0.f); }
                *(float2*)(C + (size_t)ra0 * N + col) = make_float2(v0, v1);
            }
            if (ra1 < M) {
                float v2 = acc[rg][j][2] + b0, v3 = acc[rg][j][3] + b1;
                if (RELU) { v2 = fmaxf(v2, 0.f); v3 = fmaxf(v3, 0.f); }
                *(float2*)(C + (size_t)ra1 * N + col) = make_float2(v2, v3);
            }
        }
    }
}

template <bool RELU>
__global__ void __launch_bounds__(128) gemm_bf(const float* __restrict__ A,
                                               const float* __restrict__ B,
                                               const float* __restrict__ bias,
                                               float* __restrict__ C,
                                               int M, int N, int K) {
    gemm_body<RELU>(A, B, bias, C, M, N, K, blockIdx.y << 6, blockIdx.x << 6);
}

__global__ void __launch_bounds__(128) gemm_kv_all(const float* __restrict__ mem,
                                                   const float* __restrict__ Wk,
                                                   const float* __restrict__ bk,
                                                   const float* __restrict__ Wv,
                                                   const float* __restrict__ bv,
                                                   float* __restrict__ kall,
                                                   float* __restrict__ vall) {
    const int z = blockIdx.z;
    const int l = z >> 1;
    const bool isv = z & 1;
    const float* B    = (isv ? Wv : Wk) + (size_t)l * EE * EE;
    const float* bias = (isv ? bv : bk) + (size_t)l * EE;
    float* C          = (isv ? vall : kall) + (size_t)l * MMEM * EE;
    gemm_body<false>(mem, B, bias, C, MMEM, EE, EE, blockIdx.y << 6, blockIdx.x << 6);
}

// ---------------- bf16 flash attention (QK + swapped AV, all m16n8k16) ------------
// block = 64 pair rows x 1 head, 128 thr (4 warps). No running max (|logits|<<1).
__global__ void __launch_bounds__(128) flash_bf_kernel(const float* __restrict__ Q,
                                                       const float* __restrict__ Km,
                                                       const float* __restrict__ Vm,
                                                       float* __restrict__ O) {
    const int h  = blockIdx.y;
    const int pb = blockIdx.x << 6;
    __shared__ uint32_t Qs2[64][20];   // [p][d2], bf16x2 (d even/odd), pre-scaled
    __shared__ uint32_t Ks2[16][72];   // [d2][m], u32 = (K[m][2d2], K[m][2d2+1])
    __shared__ uint32_t Vs2[32][36];   // [d][m2], u32 = (V[2m2][d], V[2m2+1][d])
    __shared__ uint32_t PT2[32][72];   // [m2][p], u32 = (P[p][2m2], P[p][2m2+1])
    __shared__ float    lsums[64];
    const int tid  = threadIdx.x;
    const int warp = tid >> 5, lane = tid & 31;
    const int qd = lane >> 2, qt = lane & 3;
    const int r0 = (warp << 4) + qd;

    {   // Q fill: 64 rows x 8 float4 slots
        const float alpha = 0.17677669529663687f;  // 1/sqrt(32)
#pragma unroll
        for (int i = 0; i < 4; i++) {
            int idx = tid + (i << 7);
            int row = idx >> 3, f4 = idx & 7;
            float4 v = *(const float4*)(Q + (size_t)(pb + row) * EE + h * DH + (f4 << 2));
            Qs2[row][f4 * 2]     = pack_bf2(v.x * alpha, v.y * alpha);
            Qs2[row][f4 * 2 + 1] = pack_bf2(v.z * alpha, v.w * alpha);
        }
    }
    float oacc[2][2][4] = {};   // [rg(d half)][j(p half)][4]
    float lsum0 = 0.f, lsum1 = 0.f;
    __syncthreads();

    for (int mb = 0; mb < MMEM; mb += 64) {
        // ---- K fill: Ks2[d2][m] ----
#pragma unroll
        for (int i = 0; i < 4; i++) {
            int idx = tid + (i << 7);
            int m = idx >> 3, f4 = idx & 7;
            float4 kv = *(const float4*)(Km + (size_t)(mb + m) * EE + h * DH + (f4 << 2));
            Ks2[f4 * 2][m]     = pack_bf2(kv.x, kv.y);
            Ks2[f4 * 2 + 1][m] = pack_bf2(kv.z, kv.w);
        }
        // ---- V fill: Vs2[d][m2] (m-pairs) ----
#pragma unroll
        for (int i = 0; i < 2; i++) {
            int idx = tid + (i << 7);
            int m2 = idx >> 3, f4 = idx & 7, d0 = f4 << 2;
            float4 v0 = *(const float4*)(Vm + (size_t)(mb + 2 * m2)     * EE + h * DH + d0);
            float4 v1 = *(const float4*)(Vm + (size_t)(mb + 2 * m2 + 1) * EE + h * DH + d0);
            Vs2[d0 + 0][m2] = pack_bf2(v0.x, v1.x);
            Vs2[d0 + 1][m2] = pack_bf2(v0.y, v1.y);
            Vs2[d0 + 2][m2] = pack_bf2(v0.z, v1.z);
            Vs2[d0 + 3][m2] = pack_bf2(v0.w, v1.w);
        }
        __syncthreads();

        // ---- QK: S[16 p][64 m] per warp, k=32 (2 k16 steps) ----
        float sacc[8][4] = {};
#pragma unroll
        for (int s = 0; s < 2; s++) {
            uint32_t a0 = Qs2[r0    ][s * 8 + qt];
            uint32_t a1 = Qs2[r0 + 8][s * 8 + qt];
            uint32_t a2 = Qs2[r0    ][s * 8 + qt + 4];
            uint32_t a3 = Qs2[r0 + 8][s * 8 + qt + 4];
#pragma unroll
            for (int j = 0; j < 8; j++) {
                uint32_t b0 = Ks2[s * 8 + qt    ][j * 8 + qd];
                uint32_t b1 = Ks2[s * 8 + qt + 4][j * 8 + qd];
                mma_bf16(sacc[j], a0, a1, a2, a3, b0, b1);
            }
        }

        // ---- exp, pack P^T (m-pairs), accumulate lsum (fp32 exact) ----
#pragma unroll
        for (int j = 0; j < 8; j++) {
            float e0 = __expf(sacc[j][0]), e1 = __expf(sacc[j][1]);
            float e2 = __expf(sacc[j][2]), e3 = __expf(sacc[j][3]);
            lsum0 += e0 + e1; lsum1 += e2 + e3;
            PT2[j * 4 + qt][r0]     = pack_bf2(e0, e1);
            PT2[j * 4 + qt][r0 + 8] = pack_bf2(e2, e3);
        }
        __syncwarp();

        // ---- AV (swapped): O^T[32 d][16 p] += V^T[32 d][64 m] @ P^T[64 m][16 p] ----
#pragma unroll
        for (int s = 0; s < 4; s++) {
            uint32_t va[2][4];
#pragma unroll
            for (int rg = 0; rg < 2; rg++) {
                int dr = (rg << 4) + qd;
                va[rg][0] = Vs2[dr    ][s * 8 + qt];
                va[rg][1] = Vs2[dr + 8][s * 8 + qt];
                va[rg][2] = Vs2[dr    ][s * 8 + qt + 4];
                va[rg][3] = Vs2[dr + 8][s * 8 + qt + 4];
            }
#pragma unroll
            for (int j = 0; j < 2; j++) {
                int pcol = (warp << 4) + j * 8 + qd;
                uint32_t b0 = PT2[s * 8 + qt    ][pcol];
                uint32_t b1 = PT2[s * 8 + qt + 4][pcol];
#pragma unroll
                for (int rg = 0; rg < 2; rg++)
                    mma_bf16(oacc[rg][j], va[rg][0], va[rg][1], va[rg][2], va[rg][3], b0, b1);
            }
        }
        __syncthreads();
    }

    // lsum: reduce over the 4 qt lanes of each row group
    lsum0 += __shfl_xor_sync(0xffffffffu, lsum0, 1);
    lsum0 += __shfl_xor_sync(0xffffffffu, lsum0, 2);
    lsum1 += __shfl_xor_sync(0xffffffffu, lsum1, 1);
    lsum1 += __shfl_xor_sync(0xffffffffu, lsum1, 2);
    if (qt == 0) { lsums[r0] = lsum0; lsums[r0 + 8] = lsum1; }
    __syncwarp();

    // output: oacc[rg][j]: c0,c1 = (d = rg*16+qd, p = w*16+j*8+2qt, +1); c2,c3 = d+8
#pragma unroll
    for (int j = 0; j < 2; j++) {
        int p0 = (warp << 4) + j * 8 + (qt << 1);
        float inv0 = 1.0f / lsums[p0];
        float inv1 = 1.0f / lsums[p0 + 1];
#pragma unroll
        for (int rg = 0; rg < 2; rg++) {
            int d = (rg << 4) + qd;
            float* o0 = O + (size_t)(pb + p0) * EE + h * DH + d;
            float* o1 = O + (size_t)(pb + p0 + 1) * EE + h * DH + d;
            o0[0] = oacc[rg][j][0] * inv0;
            o1[0] = oacc[rg][j][1] * inv1;
            o0[8] = oacc[rg][j][2] * inv0;
            o1[8] = oacc[rg][j][3] * inv1;
        }
    }
}

// q = LayerNorm(q + resid) * g + b
__global__ void add_ln_kernel(float* __restrict__ Qb, const float* __restrict__ R,
                              const float* __restrict__ g, const float* __restrict__ b) {
    const int p = blockIdx.x;
    const int e = threadIdx.x;
    __shared__ float sh[8];
    float x = Qb[(size_t)p * EE + e] + R[(size_t)p * EE + e];
    float s = x;
#pragma unroll
    for (int o = 16; o > 0; o >>= 1) s += __shfl_xor_sync(0xffffffffu, s, o);
    if ((e & 31) == 0) sh[e >> 5] = s;
    __syncthreads();
    float mean = (sh[0] + sh[1] + sh[2] + sh[3] + sh[4] + sh[5] + sh[6] + sh[7]) * (1.0f / 256.0f);
    float d = x - mean;
    __syncthreads();
    s = d * d;
#pragma unroll
    for (int o = 16; o > 0; o >>= 1) s += __shfl_xor_sync(0xffffffffu, s, o);
    if ((e & 31) == 0) sh[e >> 5] = s;
    __syncthreads();
    float var = (sh[0] + sh[1] + sh[2] + sh[3] + sh[4] + sh[5] + sh[6] + sh[7]) * (1.0f / 256.0f);
    Qb[(size_t)p * EE + e] = d * rsqrtf(var + 1e-5f) * g[e] + b[e];
}

__global__ void idx_kernel(const float* __restrict__ refs, int* __restrict__ rows,
                           int* __restrict__ cols, float* __restrict__ rfx,
                           float* __restrict__ rfy) {
    int p = blockIdx.x * blockDim.x + threadIdx.x;
    if (p >= PAIRS) return;
    int r = 0, off = 0;
    while (p >= off + (NQ - 1 - r)) { off += NQ - 1 - r; r++; }
    int c = r + 1 + (p - off);
    rows[p] = r; cols[p] = c;
    rfx[p] = 0.5f * (refs[r * 4 + 0] + refs[c * 4 + 0]);
    rfy[p] = 0.5f * (refs[r * 4 + 1] + refs[c * 4 + 1]);
}

__global__ void pairc_kernel(const float* __restrict__ H, const int* __restrict__ rows,
                             const int* __restrict__ cols, float* __restrict__ PC) {
    const int p = blockIdx.x;
    const int e = threadIdx.x;
    int r = rows[p], c = cols[p];
    PC[(size_t)p * 512 + e]       = H[r * EE + e];
    PC[(size_t)p * 512 + 256 + e] = H[c * EE + e];
}

__global__ void addref_kernel(float* __restrict__ Qb, const float* __restrict__ rfx,
                              const float* __restrict__ rfy, const float* __restrict__ Wref) {
    const int p = blockIdx.x;
    const int e = threadIdx.x;
    Qb[(size_t)p * EE + e] += rfx[p] * Wref[e] + rfy[p] * Wref[EE + e];
}

__global__ void score_kernel(const float* __restrict__ Qb, const float* __restrict__ Tx,
                             const float* __restrict__ lsc, const int* __restrict__ rows,
                             const int* __restrict__ cols, float* __restrict__ out) {
    const int pp = blockIdx.x;
    __shared__ float qr[EE];
    const int tid = threadIdx.x;
    qr[tid] = Qb[(size_t)pp * EE + tid];
    __syncthreads();
    const float scale = expf(lsc[0]);
    const int w = tid >> 5, lane = tid & 31;
    const int r = rows[pp], c = cols[pp];
    for (int t = w; t < TTXT; t += 8) {
        float sum = 0.0f;
#pragma unroll
        for (int i = 0; i < 8; i++)
            sum = fmaf(qr[lane + (i << 5)], Tx[(size_t)t * EE + lane + (i << 5)], sum);
#pragma unroll
        for (int o = 16; o > 0; o >>= 1) sum += __shfl_down_sync(0xffffffffu, sum, o);
        if (lane == 0) {
            float vv = sum * scale;
            out[(size_t)(r * NQ + c) * TTXT + t] = vv;
            out[(size_t)(c * NQ + r) * TTXT + t] = vv;
        }
    }
}

// ----------------------------------- launcher ------------------------------------
extern "C" void kernel_launch(void* const* d_in, const int* in_sizes, int n_in,
                              void* d_out, int out_size) {
    const float* hid    = (const float*)d_in[0];
    const float* memin  = (const float*)d_in[1];
    const float* refs   = (const float*)d_in[2];
    const float* mtext  = (const float*)d_in[3];
    const float* W_pair = (const float*)d_in[6];
    const float* b_pair = (const float*)d_in[7];
    const float* W_mem  = (const float*)d_in[8];
    const float* b_mem  = (const float*)d_in[9];
    const float* W_text = (const float*)d_in[10];
    const float* b_text = (const float*)d_in[11];
    const float* W_ref  = (const float*)d_in[12];
    const float* Wq = (const float*)d_in[13]; const float* bq = (const float*)d_in[14];
    const float* Wk = (const float*)d_in[15]; const float* bk = (const float*)d_in[16];
    const float* Wv = (const float*)d_in[17]; const float* bv = (const float*)d_in[18];
    const float* Wo = (const float*)d_in[19]; const float* bo = (const float*)d_in[20];
    const float* ln1g = (const float*)d_in[21]; const float* ln1b = (const float*)d_in[22];
    const float* ln2g = (const float*)d_in[23]; const float* ln2b = (const float*)d_in[24];
    const float* Wf1 = (const float*)d_in[25]; const float* bf1 = (const float*)d_in[26];
    const float* Wf2 = (const float*)d_in[27]; const float* bf2 = (const float*)d_in[28];
    const float* lsc = (const float*)d_in[29];
    float* out = (float*)d_out;

    float *pc, *q, *qh, *mem, *kall, *vall, *attn, *proj, *ffb, *text, *rfx, *rfy;
    int *rowp, *colp;
    cudaGetSymbolAddress((void**)&pc,   g_pairconcat);
    cudaGetSymbolAddress((void**)&q,    g_q);
    cudaGetSymbolAddress((void**)&qh,   g_qh);
    cudaGetSymbolAddress((void**)&mem,  g_mem);
    cudaGetSymbolAddress((void**)&kall, g_kall);
    cudaGetSymbolAddress((void**)&vall, g_vall);
    cudaGetSymbolAddress((void**)&attn, g_attn);
    cudaGetSymbolAddress((void**)&proj, g_proj);
    cudaGetSymbolAddress((void**)&ffb,  g_ffb);
    cudaGetSymbolAddress((void**)&text, g_text);
    cudaGetSymbolAddress((void**)&rowp, g_rowi);
    cudaGetSymbolAddress((void**)&colp, g_coli);
    cudaGetSymbolAddress((void**)&rfx,  g_refx);
    cudaGetSymbolAddress((void**)&rfy,  g_refy);

    idx_kernel<<<8, 256>>>(refs, rowp, colp, rfx, rfy);
    pairc_kernel<<<PAIRS, 256>>>(hid, rowp, colp, pc);
    gemm_bf<false><<<dim3(4, 32), 128>>>(pc, W_pair, b_pair, q, PAIRS, EE, 512);
    addref_kernel<<<PAIRS, 256>>>(q, rfx, rfy, W_ref);
    gemm_bf<false><<<dim3(4, 64), 128>>>(memin, W_mem, b_mem, mem, MMEM, EE, EE);
    gemm_bf<false><<<dim3(4, 1), 128>>>(mtext, W_text, b_text, text, TTXT, EE, EE);
    gemm_kv_all<<<dim3(4, 64, 2 * LLAYERS), 128>>>(mem, Wk, bk, Wv, bv, kall, vall);

    for (int l = 0; l < LLAYERS; l++) {
        gemm_bf<false><<<dim3(4, 32), 128>>>(q, Wq + (size_t)l * EE * EE, bq + l * EE, qh, PAIRS, EE, EE);
        flash_bf_kernel<<<dim3(PPAD / 64, HN), 128>>>(qh, kall + (size_t)l * MMEM * EE,
                                                      vall + (size_t)l * MMEM * EE, attn);
        gemm_bf<false><<<dim3(4, 32), 128>>>(attn, Wo + (size_t)l * EE * EE, bo + l * EE, proj, PAIRS, EE, EE);
        add_ln_kernel<<<PAIRS, 256>>>(q, proj, ln1g + l * EE, ln1b + l * EE);
        gemm_bf<true ><<<dim3(16, 32), 128>>>(q, Wf1 + (size_t)l * EE * FFD, bf1 + l * FFD, ffb, PAIRS, FFD, EE);
        gemm_bf<false><<<dim3(4, 32), 128>>>(ffb, Wf2 + (size_t)l * FFD * EE, bf2 + l * EE, proj, PAIRS, EE, FFD);
        add_ln_kernel<<<PAIRS, 256>>>(q, proj, ln2g + l * EE, ln2b + l * EE);
    }

    cudaMemsetAsync(d_out, 0, (size_t)out_size * sizeof(float), 0);
    score_kernel<<<PAIRS, 256>>>(q, text, lsc, rowp, colp, out);
}